// round 2
// baseline (speedup 1.0000x reference)
#include <cuda_runtime.h>
#include <cuda_bf16.h>
#include <math.h>

#define NEG_INF_F (-1e30f)

static constexpr int B = 64;
static constexpr int C = 1024;
static constexpr int Q = 128;
static constexpr int H = 512;

// ---------------- scratch (device globals: allocation-free rule) ----------------
__device__ float g_qw[(size_t)B * Q * H];      // x_query * W2        (16 MB)
__device__ float g_sub0[B * Q];
__device__ float g_sub1[B * C];
__device__ float g_S[(size_t)B * C * Q];       // S, then S_ in place (33.5 MB)
__device__ float g_Sc[(size_t)B * C * Q];      // softmax over c      (33.5 MB)
__device__ float g_tmp[(size_t)B * Q * H];     // S_c^T @ Xc          (16 MB)

// ---------------- small helpers ----------------
__device__ __forceinline__ float block_reduce_sum_128(float v, float* red) {
    int t = threadIdx.x;
    #pragma unroll
    for (int o = 16; o > 0; o >>= 1) v += __shfl_xor_sync(0xffffffffu, v, o);
    if ((t & 31) == 0) red[t >> 5] = v;
    __syncthreads();
    return red[0] + red[1] + red[2] + red[3];
}

// ---------------- prep kernels ----------------
// block per (b,q): write qw = xq*W2, reduce sub0 = dot(xq, W0)
__global__ void prep_query_kernel(const float* __restrict__ xq,
                                  const float* __restrict__ W0,
                                  const float* __restrict__ W2,
                                  float* __restrict__ qw,
                                  float* __restrict__ sub0) {
    int bq = blockIdx.x;
    int t = threadIdx.x;
    const float* row = xq + (size_t)bq * H;
    float* orow = qw + (size_t)bq * H;
    float s = 0.f;
    #pragma unroll
    for (int i = 0; i < H / 128; i++) {
        int h = i * 128 + t;
        float v = row[h];
        orow[h] = v * W2[h];
        s = fmaf(v, W0[h], s);
    }
    __shared__ float red[4];
    s = block_reduce_sum_128(s, red);
    if (t == 0) sub0[bq] = s;
}

// block per (b,c): sub1 = dot(xc, W1)
__global__ void prep_context_kernel(const float* __restrict__ xc,
                                    const float* __restrict__ W1,
                                    float* __restrict__ sub1) {
    int bc = blockIdx.x;
    int t = threadIdx.x;
    const float* row = xc + (size_t)bc * H;
    float s = 0.f;
    #pragma unroll
    for (int i = 0; i < H / 128; i++) {
        int h = i * 128 + t;
        s = fmaf(row[h], W1[h], s);
    }
    __shared__ float red[4];
    s = block_reduce_sum_128(s, red);
    if (t == 0) sub1[bc] = s;
}

// ---------------- generic batched SGEMM ----------------
// C[m,n] = sum_k A(m,k) * B(n,k)   (+ rowBias[m] + colBias[n] + *scalarBias)
// AMODE 0: A is MxK row-major (A[m*lda+k]);  AMODE 1: A is KxM row-major (A[k*lda+m])
// BMODE 0: B is NxK row-major (B[n*ldb+k]);  BMODE 1: B is KxN row-major (B[k*ldb+n])
template <int BM, int BN, int BK, int TM, int TN, int AMODE, int BMODE>
__global__ void __launch_bounds__((BM / TM) * (BN / TN))
sgemm_kernel(const float* __restrict__ A, const float* __restrict__ Bp,
             float* __restrict__ Cp, int M, int N, int K,
             int lda, int ldb, int ldc,
             size_t sA, size_t sB, size_t sC,
             const float* __restrict__ rowBias, int rbStride,
             const float* __restrict__ colBias, int cbStride,
             const float* __restrict__ scalarBias) {
    constexpr int THREADS = (BM / TM) * (BN / TN);
    constexpr int PAD = 4;
    __shared__ float As[BK][BM + PAD];
    __shared__ float Bs[BK][BN + PAD];

    const int bz = blockIdx.z;
    A += (size_t)bz * sA;
    Bp += (size_t)bz * sB;
    Cp += (size_t)bz * sC;
    const int tileM = blockIdx.y * BM;
    const int tileN = blockIdx.x * BN;
    const int tid = threadIdx.x;
    const int tx = tid % (BN / TN);
    const int ty = tid / (BN / TN);

    float acc[TM][TN] = {};

    for (int k0 = 0; k0 < K; k0 += BK) {
        if (AMODE == 0) {
            constexpr int KV = BK / 4;
            #pragma unroll
            for (int i = tid; i < BM * KV; i += THREADS) {
                int row = i / KV, kc = (i % KV) * 4;
                float4 v = *(const float4*)(A + (size_t)(tileM + row) * lda + k0 + kc);
                As[kc + 0][row] = v.x; As[kc + 1][row] = v.y;
                As[kc + 2][row] = v.z; As[kc + 3][row] = v.w;
            }
        } else {
            constexpr int MV = BM / 4;
            #pragma unroll
            for (int i = tid; i < BK * MV; i += THREADS) {
                int kr = i / MV, mc = (i % MV) * 4;
                *(float4*)&As[kr][mc] =
                    *(const float4*)(A + (size_t)(k0 + kr) * lda + tileM + mc);
            }
        }
        if (BMODE == 0) {
            constexpr int KV = BK / 4;
            #pragma unroll
            for (int i = tid; i < BN * KV; i += THREADS) {
                int row = i / KV, kc = (i % KV) * 4;
                float4 v = *(const float4*)(Bp + (size_t)(tileN + row) * ldb + k0 + kc);
                Bs[kc + 0][row] = v.x; Bs[kc + 1][row] = v.y;
                Bs[kc + 2][row] = v.z; Bs[kc + 3][row] = v.w;
            }
        } else {
            constexpr int NV = BN / 4;
            #pragma unroll
            for (int i = tid; i < BK * NV; i += THREADS) {
                int kr = i / NV, nc = (i % NV) * 4;
                *(float4*)&Bs[kr][nc] =
                    *(const float4*)(Bp + (size_t)(k0 + kr) * ldb + tileN + nc);
            }
        }
        __syncthreads();
        #pragma unroll
        for (int kk = 0; kk < BK; kk++) {
            float af[TM], bf[TN];
            #pragma unroll
            for (int i = 0; i < TM; i += 4)
                *(float4*)&af[i] = *(const float4*)&As[kk][ty * TM + i];
            #pragma unroll
            for (int j = 0; j < TN; j += 4)
                *(float4*)&bf[j] = *(const float4*)&Bs[kk][tx * TN + j];
            #pragma unroll
            for (int i = 0; i < TM; i++)
                #pragma unroll
                for (int j = 0; j < TN; j++)
                    acc[i][j] = fmaf(af[i], bf[j], acc[i][j]);
        }
        __syncthreads();
    }

    const float sb = scalarBias ? __ldg(scalarBias) : 0.f;
    #pragma unroll
    for (int i = 0; i < TM; i++) {
        int m = tileM + ty * TM + i;
        float rb = rowBias ? rowBias[bz * rbStride + m] : 0.f;
        #pragma unroll
        for (int j = 0; j < TN; j += 4) {
            int n = tileN + tx * TN + j;
            float4 w;
            w.x = acc[i][j + 0] + rb + (colBias ? colBias[bz * cbStride + n + 0] : 0.f) + sb;
            w.y = acc[i][j + 1] + rb + (colBias ? colBias[bz * cbStride + n + 1] : 0.f) + sb;
            w.z = acc[i][j + 2] + rb + (colBias ? colBias[bz * cbStride + n + 2] : 0.f) + sb;
            w.w = acc[i][j + 3] + rb + (colBias ? colBias[bz * cbStride + n + 3] : 0.f) + sb;
            *(float4*)(Cp + (size_t)m * ldc + n) = w;
        }
    }
}

// ---------------- softmaxes ----------------
// softmax over c (axis=1): block per b, thread = q; online max/sum, then write pass
__global__ void softmax_c_kernel(const float* __restrict__ S,
                                 const float* __restrict__ cmask,
                                 float* __restrict__ Sc) {
    int b = blockIdx.x;
    int q = threadIdx.x;
    const float* Sb = S + (size_t)b * C * Q;
    float* Ob = Sc + (size_t)b * C * Q;
    const float* mcb = cmask + (size_t)b * C;
    float m = -INFINITY, s = 0.f;
    for (int c = 0; c < C; c++) {
        float add = (1.f - mcb[c]) * NEG_INF_F;
        float v = Sb[(size_t)c * Q + q] + add;
        float mn = fmaxf(m, v);
        s = s * __expf(m - mn) + __expf(v - mn);
        m = mn;
    }
    float inv = 1.f / s;
    for (int c = 0; c < C; c++) {
        float add = (1.f - mcb[c]) * NEG_INF_F;
        float v = Sb[(size_t)c * Q + q] + add;
        Ob[(size_t)c * Q + q] = __expf(v - m) * inv;
    }
}

// softmax over q (axis=-1), in place: block per row (b*C + c), thread = q
__global__ void softmax_q_kernel(float* __restrict__ S,
                                 const float* __restrict__ qmask) {
    int row = blockIdx.x;           // b*C + c
    int b = row >> 10;              // C = 1024
    int q = threadIdx.x;
    float* Sr = S + (size_t)row * Q;
    float v = Sr[q] + (1.f - qmask[b * Q + q]) * NEG_INF_F;

    __shared__ float red[4];
    float m = v;
    #pragma unroll
    for (int o = 16; o > 0; o >>= 1) m = fmaxf(m, __shfl_xor_sync(0xffffffffu, m, o));
    if ((q & 31) == 0) red[q >> 5] = m;
    __syncthreads();
    m = fmaxf(fmaxf(red[0], red[1]), fmaxf(red[2], red[3]));
    __syncthreads();

    float e = __expf(v - m);
    float s = e;
    #pragma unroll
    for (int o = 16; o > 0; o >>= 1) s += __shfl_xor_sync(0xffffffffu, s, o);
    if ((q & 31) == 0) red[q >> 5] = s;
    __syncthreads();
    s = red[0] + red[1] + red[2] + red[3];
    Sr[q] = e / s;
}

// ---------------- launch ----------------
extern "C" void kernel_launch(void* const* d_in, const int* in_sizes, int n_in,
                              void* d_out, int out_size) {
    const float* x_context   = (const float*)d_in[0];  // B,C,H
    const float* x_query     = (const float*)d_in[1];  // B,Q,H
    const float* context_mask= (const float*)d_in[2];  // B,C
    const float* query_mask  = (const float*)d_in[3];  // B,Q
    const float* W0          = (const float*)d_in[4];
    const float* W1          = (const float*)d_in[5];
    const float* W2          = (const float*)d_in[6];
    const float* bias        = (const float*)d_in[7];
    float* out = (float*)d_out;                         // [c2q | q2c], each B*C*H

    float *p_qw, *p_sub0, *p_sub1, *p_S, *p_Sc, *p_tmp;
    cudaGetSymbolAddress((void**)&p_qw,   g_qw);
    cudaGetSymbolAddress((void**)&p_sub0, g_sub0);
    cudaGetSymbolAddress((void**)&p_sub1, g_sub1);
    cudaGetSymbolAddress((void**)&p_S,    g_S);
    cudaGetSymbolAddress((void**)&p_Sc,   g_Sc);
    cudaGetSymbolAddress((void**)&p_tmp,  g_tmp);

    const size_t BCH = (size_t)B * C * H;

    // 1. prep
    prep_query_kernel<<<B * Q, 128>>>(x_query, W0, W2, p_qw, p_sub0);
    prep_context_kernel<<<B * C, 128>>>(x_context, W1, p_sub1);

    // 2. S = Xc @ (Xq*W2)^T + sub1[c] + sub0[q] + bias   (NT)
    sgemm_kernel<128, 128, 16, 8, 8, 0, 0><<<dim3(Q / 128, C / 128, B), 256>>>(
        x_context, p_qw, p_S, C, Q, H, H, H, Q,
        (size_t)C * H, (size_t)Q * H, (size_t)C * Q,
        p_sub1, C, p_sub0, Q, bias);

    // 3. softmax over c -> g_Sc ; then softmax over q in place on g_S
    softmax_c_kernel<<<B, 128>>>(p_S, context_mask, p_Sc);
    softmax_q_kernel<<<B * C, 128>>>(p_S, query_mask);

    // 4. tmp = S_c^T @ Xc   (TN): M=Q, N=H, K=C
    sgemm_kernel<128, 128, 16, 8, 8, 1, 1><<<dim3(H / 128, Q / 128, B), 256>>>(
        p_Sc, x_context, p_tmp, Q, H, C, Q, H, H,
        (size_t)C * Q, (size_t)C * H, (size_t)Q * H,
        nullptr, 0, nullptr, 0, nullptr);

    // 5. c2q = S_ @ Xq   (NN): M=C, N=H, K=Q
    sgemm_kernel<128, 128, 16, 8, 8, 0, 1><<<dim3(H / 128, C / 128, B), 256>>>(
        p_S, x_query, out, C, H, Q, Q, H, H,
        (size_t)C * Q, (size_t)Q * H, (size_t)C * H,
        nullptr, 0, nullptr, 0, nullptr);

    // 6. q2c = S_ @ tmp  (NN): M=C, N=H, K=Q
    sgemm_kernel<128, 128, 16, 8, 8, 0, 1><<<dim3(H / 128, C / 128, B), 256>>>(
        p_S, p_tmp, out + BCH, C, H, Q, Q, H, H,
        (size_t)C * Q, (size_t)Q * H, (size_t)C * H,
        nullptr, 0, nullptr, 0, nullptr);
}

// round 3
// speedup vs baseline: 2.1959x; 2.1959x over previous
#include <cuda_runtime.h>
#include <cuda_bf16.h>
#include <math.h>

#define NEG_INF_F (-1e30f)

static constexpr int B = 64;
static constexpr int C = 1024;
static constexpr int Q = 128;
static constexpr int H = 512;
static constexpr int NCH = 32;          // softmax_c chunks (C/NCH = 32 rows each)

// ---------------- scratch (device globals: allocation-free rule) ----------------
__device__ float g_qw[(size_t)B * Q * H];      // x_query * W2        (16 MB)
__device__ float g_sub0[B * Q];
__device__ float g_sub1[B * C];
__device__ float g_S[(size_t)B * C * Q];       // S, then S_ in place (33.5 MB)
__device__ float g_Sc[(size_t)B * C * Q];      // softmax over c      (33.5 MB)
__device__ float g_tmp[(size_t)B * Q * H];     // S_c^T @ Xc          (16 MB)
__device__ float g_pm[B * NCH * Q];
__device__ float g_ps[B * NCH * Q];
__device__ float g_gm[B * Q];
__device__ float g_ginv[B * Q];

// ---------------- helpers ----------------
__device__ __forceinline__ float to_tf32(float x) {
    asm("cvt.rna.tf32.f32 %0, %1;" : "=f"(x) : "f"(x));
    return x;
}

__device__ __forceinline__ void mma_tf32(float* c, const unsigned* a, const unsigned* b) {
    asm volatile(
        "mma.sync.aligned.m16n8k8.row.col.f32.tf32.tf32.f32 "
        "{%0,%1,%2,%3}, {%4,%5,%6,%7}, {%8,%9}, {%0,%1,%2,%3};"
        : "+f"(c[0]), "+f"(c[1]), "+f"(c[2]), "+f"(c[3])
        : "r"(a[0]), "r"(a[1]), "r"(a[2]), "r"(a[3]), "r"(b[0]), "r"(b[1]));
}

__device__ __forceinline__ float block_reduce_sum_128(float v, float* red) {
    int t = threadIdx.x;
    #pragma unroll
    for (int o = 16; o > 0; o >>= 1) v += __shfl_xor_sync(0xffffffffu, v, o);
    if ((t & 31) == 0) red[t >> 5] = v;
    __syncthreads();
    return red[0] + red[1] + red[2] + red[3];
}

// ---------------- prep kernels ----------------
__global__ void prep_query_kernel(const float* __restrict__ xq,
                                  const float* __restrict__ W0,
                                  const float* __restrict__ W2,
                                  float* __restrict__ qw,
                                  float* __restrict__ sub0) {
    int bq = blockIdx.x;
    int t = threadIdx.x;
    const float* row = xq + (size_t)bq * H;
    float* orow = qw + (size_t)bq * H;
    float s = 0.f;
    #pragma unroll
    for (int i = 0; i < H / 128; i++) {
        int h = i * 128 + t;
        float v = row[h];
        orow[h] = v * W2[h];
        s = fmaf(v, W0[h], s);
    }
    __shared__ float red[4];
    s = block_reduce_sum_128(s, red);
    if (t == 0) sub0[bq] = s;
}

__global__ void prep_context_kernel(const float* __restrict__ xc,
                                    const float* __restrict__ W1,
                                    float* __restrict__ sub1) {
    int bc = blockIdx.x;
    int t = threadIdx.x;
    const float* row = xc + (size_t)bc * H;
    float s = 0.f;
    #pragma unroll
    for (int i = 0; i < H / 128; i++) {
        int h = i * 128 + t;
        s = fmaf(row[h], W1[h], s);
    }
    __shared__ float red[4];
    s = block_reduce_sum_128(s, red);
    if (t == 0) sub1[bc] = s;
}

// ---------------- tf32 tensor-core batched GEMM ----------------
// D[m,n] = sum_k A(m,k)*B(n,k) (+rowBias[m] + colBias[n] + *scalarBias)
// AMODE 0: A row-major MxK (A[m*lda+k]); AMODE 1: A row-major KxM (A[k*lda+m])
// BMODE 0: B row-major NxK (B[n*ldb+k]); BMODE 1: B row-major KxN (B[k*ldb+n])
// Tiles: 128x128x16, 8 warps; warp tile 64x32 (4x m16 x 4x n8 per k8 step).
template <int AMODE, int BMODE>
__global__ void __launch_bounds__(256)
gemm_tf32_kernel(const float* __restrict__ A, const float* __restrict__ Bp,
                 float* __restrict__ Cp, int K,
                 int lda, int ldb, int ldc,
                 size_t sA, size_t sB, size_t sC,
                 const float* __restrict__ rowBias, int rbStride,
                 const float* __restrict__ colBias, int cbStride,
                 const float* __restrict__ scalarBias) {
    constexpr int BM = 128, BN = 128, BK = 16, PAD = 8;
    __shared__ float As[BK][BM + PAD];
    __shared__ float Bs[BK][BN + PAD];

    const int bz = blockIdx.z;
    A  += (size_t)bz * sA;
    Bp += (size_t)bz * sB;
    Cp += (size_t)bz * sC;
    const int tileM = blockIdx.y * BM;
    const int tileN = blockIdx.x * BN;
    const int tid = threadIdx.x;
    const int wid = tid >> 5, lane = tid & 31;
    const int warpM = (wid & 1) * 64;
    const int warpN = (wid >> 1) * 32;
    const int g = lane >> 2, tg = lane & 3;

    float acc[4][4][4] = {};

    for (int k0 = 0; k0 < K; k0 += BK) {
        // ---- stage A ----
        if (AMODE == 0) {
            #pragma unroll
            for (int i = tid; i < BM * (BK / 4); i += 256) {
                int m = i / (BK / 4), kc = (i % (BK / 4)) * 4;
                float4 v = *(const float4*)(A + (size_t)(tileM + m) * lda + k0 + kc);
                As[kc + 0][m] = to_tf32(v.x); As[kc + 1][m] = to_tf32(v.y);
                As[kc + 2][m] = to_tf32(v.z); As[kc + 3][m] = to_tf32(v.w);
            }
        } else {
            #pragma unroll
            for (int i = tid; i < BK * (BM / 4); i += 256) {
                int k = i / (BM / 4), mc = (i % (BM / 4)) * 4;
                float4 v = *(const float4*)(A + (size_t)(k0 + k) * lda + tileM + mc);
                As[k][mc + 0] = to_tf32(v.x); As[k][mc + 1] = to_tf32(v.y);
                As[k][mc + 2] = to_tf32(v.z); As[k][mc + 3] = to_tf32(v.w);
            }
        }
        // ---- stage B ----
        if (BMODE == 0) {
            #pragma unroll
            for (int i = tid; i < BN * (BK / 4); i += 256) {
                int n = i / (BK / 4), kc = (i % (BK / 4)) * 4;
                float4 v = *(const float4*)(Bp + (size_t)(tileN + n) * ldb + k0 + kc);
                Bs[kc + 0][n] = to_tf32(v.x); Bs[kc + 1][n] = to_tf32(v.y);
                Bs[kc + 2][n] = to_tf32(v.z); Bs[kc + 3][n] = to_tf32(v.w);
            }
        } else {
            #pragma unroll
            for (int i = tid; i < BK * (BN / 4); i += 256) {
                int k = i / (BN / 4), nc = (i % (BN / 4)) * 4;
                float4 v = *(const float4*)(Bp + (size_t)(k0 + k) * ldb + tileN + nc);
                Bs[k][nc + 0] = to_tf32(v.x); Bs[k][nc + 1] = to_tf32(v.y);
                Bs[k][nc + 2] = to_tf32(v.z); Bs[k][nc + 3] = to_tf32(v.w);
            }
        }
        __syncthreads();

        #pragma unroll
        for (int ks = 0; ks < BK; ks += 8) {
            unsigned af[4][4], bf[4][2];
            #pragma unroll
            for (int mt = 0; mt < 4; mt++) {
                int m0 = warpM + mt * 16;
                af[mt][0] = __float_as_uint(As[ks + tg    ][m0 + g    ]);
                af[mt][1] = __float_as_uint(As[ks + tg    ][m0 + g + 8]);
                af[mt][2] = __float_as_uint(As[ks + tg + 4][m0 + g    ]);
                af[mt][3] = __float_as_uint(As[ks + tg + 4][m0 + g + 8]);
            }
            #pragma unroll
            for (int nt = 0; nt < 4; nt++) {
                int n0 = warpN + nt * 8;
                bf[nt][0] = __float_as_uint(Bs[ks + tg    ][n0 + g]);
                bf[nt][1] = __float_as_uint(Bs[ks + tg + 4][n0 + g]);
            }
            #pragma unroll
            for (int mt = 0; mt < 4; mt++)
                #pragma unroll
                for (int nt = 0; nt < 4; nt++)
                    mma_tf32(acc[mt][nt], af[mt], bf[nt]);
        }
        __syncthreads();
    }

    // ---- epilogue ----
    const float sb = scalarBias ? __ldg(scalarBias) : 0.f;
    #pragma unroll
    for (int mt = 0; mt < 4; mt++) {
        int r0 = tileM + warpM + mt * 16 + g;
        int r1 = r0 + 8;
        float rb0 = rowBias ? rowBias[bz * rbStride + r0] + sb : sb;
        float rb1 = rowBias ? rowBias[bz * rbStride + r1] + sb : sb;
        #pragma unroll
        for (int nt = 0; nt < 4; nt++) {
            int c0 = tileN + warpN + nt * 8 + tg * 2;
            float cb0 = colBias ? colBias[bz * cbStride + c0    ] : 0.f;
            float cb1 = colBias ? colBias[bz * cbStride + c0 + 1] : 0.f;
            Cp[(size_t)r0 * ldc + c0    ] = acc[mt][nt][0] + rb0 + cb0;
            Cp[(size_t)r0 * ldc + c0 + 1] = acc[mt][nt][1] + rb0 + cb1;
            Cp[(size_t)r1 * ldc + c0    ] = acc[mt][nt][2] + rb1 + cb0;
            Cp[(size_t)r1 * ldc + c0 + 1] = acc[mt][nt][3] + rb1 + cb1;
        }
    }
}

// ---------------- softmax over c (axis=1): 3-phase, full-chip parallel ----------------
__global__ void softc_partial(const float* __restrict__ S,
                              const float* __restrict__ cmask,
                              float* __restrict__ pm, float* __restrict__ ps) {
    int chunk = blockIdx.x, b = blockIdx.y;
    int q = threadIdx.x;
    constexpr int RB = C / NCH;
    const float* Sb = S + ((size_t)b * C + chunk * RB) * Q + q;
    const float* mcb = cmask + (size_t)b * C + chunk * RB;
    float m = -INFINITY, s = 0.f;
    #pragma unroll 4
    for (int c = 0; c < RB; c++) {
        float v = Sb[(size_t)c * Q] + (1.f - mcb[c]) * NEG_INF_F;
        float mn = fmaxf(m, v);
        s = s * __expf(m - mn) + __expf(v - mn);
        m = mn;
    }
    pm[(b * NCH + chunk) * Q + q] = m;
    ps[(b * NCH + chunk) * Q + q] = s;
}

__global__ void softc_combine(const float* __restrict__ pm,
                              const float* __restrict__ ps,
                              float* __restrict__ gm, float* __restrict__ ginv) {
    int b = blockIdx.x, q = threadIdx.x;
    float m = -INFINITY;
    #pragma unroll
    for (int ch = 0; ch < NCH; ch++)
        m = fmaxf(m, pm[(b * NCH + ch) * Q + q]);
    float s = 0.f;
    #pragma unroll
    for (int ch = 0; ch < NCH; ch++)
        s += ps[(b * NCH + ch) * Q + q] * __expf(pm[(b * NCH + ch) * Q + q] - m);
    gm[b * Q + q] = m;
    ginv[b * Q + q] = 1.f / s;
}

__global__ void softc_write(const float* __restrict__ S,
                            const float* __restrict__ cmask,
                            const float* __restrict__ gm,
                            const float* __restrict__ ginv,
                            float* __restrict__ Sc) {
    int chunk = blockIdx.x, b = blockIdx.y;
    int q = threadIdx.x;
    constexpr int RB = C / NCH;
    float m = gm[b * Q + q];
    float inv = ginv[b * Q + q];
    size_t base = ((size_t)b * C + chunk * RB) * Q + q;
    const float* mcb = cmask + (size_t)b * C + chunk * RB;
    #pragma unroll 4
    for (int c = 0; c < RB; c++) {
        float v = S[base + (size_t)c * Q] + (1.f - mcb[c]) * NEG_INF_F;
        Sc[base + (size_t)c * Q] = __expf(v - m) * inv;
    }
}

// ---------------- softmax over q (axis=-1), in place: warp per row ----------------
__global__ void softmax_q_kernel(float* __restrict__ S,
                                 const float* __restrict__ qmask) {
    int row = blockIdx.x * 8 + (threadIdx.x >> 5);   // b*C + c
    int lane = threadIdx.x & 31;
    int b = row >> 10;                               // C = 1024
    float* Sr = S + (size_t)row * Q;
    const float* mq = qmask + b * Q;

    float v[4];
    #pragma unroll
    for (int i = 0; i < 4; i++) {
        int q = lane + i * 32;
        v[i] = Sr[q] + (1.f - mq[q]) * NEG_INF_F;
    }
    float m = fmaxf(fmaxf(v[0], v[1]), fmaxf(v[2], v[3]));
    #pragma unroll
    for (int o = 16; o > 0; o >>= 1) m = fmaxf(m, __shfl_xor_sync(0xffffffffu, m, o));
    float s = 0.f;
    #pragma unroll
    for (int i = 0; i < 4; i++) { v[i] = __expf(v[i] - m); s += v[i]; }
    #pragma unroll
    for (int o = 16; o > 0; o >>= 1) s += __shfl_xor_sync(0xffffffffu, s, o);
    float inv = 1.f / s;
    #pragma unroll
    for (int i = 0; i < 4; i++) Sr[lane + i * 32] = v[i] * inv;
}

// ---------------- launch ----------------
extern "C" void kernel_launch(void* const* d_in, const int* in_sizes, int n_in,
                              void* d_out, int out_size) {
    const float* x_context    = (const float*)d_in[0];  // B,C,H
    const float* x_query      = (const float*)d_in[1];  // B,Q,H
    const float* context_mask = (const float*)d_in[2];  // B,C
    const float* query_mask   = (const float*)d_in[3];  // B,Q
    const float* W0           = (const float*)d_in[4];
    const float* W1           = (const float*)d_in[5];
    const float* W2           = (const float*)d_in[6];
    const float* bias         = (const float*)d_in[7];
    float* out = (float*)d_out;                          // [c2q | q2c], each B*C*H

    float *p_qw, *p_sub0, *p_sub1, *p_S, *p_Sc, *p_tmp, *p_pm, *p_ps, *p_gm, *p_ginv;
    cudaGetSymbolAddress((void**)&p_qw,   g_qw);
    cudaGetSymbolAddress((void**)&p_sub0, g_sub0);
    cudaGetSymbolAddress((void**)&p_sub1, g_sub1);
    cudaGetSymbolAddress((void**)&p_S,    g_S);
    cudaGetSymbolAddress((void**)&p_Sc,   g_Sc);
    cudaGetSymbolAddress((void**)&p_tmp,  g_tmp);
    cudaGetSymbolAddress((void**)&p_pm,   g_pm);
    cudaGetSymbolAddress((void**)&p_ps,   g_ps);
    cudaGetSymbolAddress((void**)&p_gm,   g_gm);
    cudaGetSymbolAddress((void**)&p_ginv, g_ginv);

    const size_t BCH = (size_t)B * C * H;

    // 1. prep
    prep_query_kernel<<<B * Q, 128>>>(x_query, W0, W2, p_qw, p_sub0);
    prep_context_kernel<<<B * C, 128>>>(x_context, W1, p_sub1);

    // 2. S = Xc @ (Xq*W2)^T + sub1[c] + sub0[q] + bias
    gemm_tf32_kernel<0, 0><<<dim3(Q / 128, C / 128, B), 256>>>(
        x_context, p_qw, p_S, H, H, H, Q,
        (size_t)C * H, (size_t)Q * H, (size_t)C * Q,
        p_sub1, C, p_sub0, Q, bias);

    // 3. softmax over c -> g_Sc ; softmax over q in place on g_S
    softc_partial<<<dim3(NCH, B), Q>>>(p_S, context_mask, p_pm, p_ps);
    softc_combine<<<B, Q>>>(p_pm, p_ps, p_gm, p_ginv);
    softc_write<<<dim3(NCH, B), Q>>>(p_S, context_mask, p_gm, p_ginv, p_Sc);
    softmax_q_kernel<<<B * C / 8, 256>>>(p_S, query_mask);

    // 4. tmp = S_c^T @ Xc   (M=Q, N=H, K=C)
    gemm_tf32_kernel<1, 1><<<dim3(H / 128, Q / 128, B), 256>>>(
        p_Sc, x_context, p_tmp, C, Q, H, H,
        (size_t)C * Q, (size_t)C * H, (size_t)Q * H,
        nullptr, 0, nullptr, 0, nullptr);

    // 5. c2q = S_ @ Xq   (M=C, N=H, K=Q)
    gemm_tf32_kernel<0, 1><<<dim3(H / 128, C / 128, B), 256>>>(
        p_S, x_query, out, Q, Q, H, H,
        (size_t)C * Q, (size_t)Q * H, (size_t)C * H,
        nullptr, 0, nullptr, 0, nullptr);

    // 6. q2c = S_ @ tmp  (M=C, N=H, K=Q)
    gemm_tf32_kernel<0, 1><<<dim3(H / 128, C / 128, B), 256>>>(
        p_S, p_tmp, out + BCH, Q, Q, H, H,
        (size_t)C * Q, (size_t)Q * H, (size_t)C * H,
        nullptr, 0, nullptr, 0, nullptr);
}